// round 5
// baseline (speedup 1.0000x reference)
#include <cuda_runtime.h>
#include <cuda_bf16.h>

// GlobalContextBlock (GCNet), fully fused persistent kernel.
// Shapes fixed: B=32, H=W=64 (HW=4096), C=256, HEADS=8, c1=32, planes=64.
//
// One kernel, grid = B*4 = 128 blocks x 512 threads (co-resident on 148 SMs),
// two spin grid-barriers (generation-counter based, graph-replay safe):
//   phase 1: each warp owns one contiguous superchunk (64 positions x 256 ch)
//            and computes softmax-pooling partials (exp w/o max: |logit|<~7).
//   mlp:     blocks 0..B-1 reduce partials -> ctx -> MLP -> g_term.
//   phase 2: each warp re-walks ITS OWN superchunk in REVERSE order doing
//            out = x + term. L1 is not flushed within a launch, and L2 holds
//            ~all of x at the barrier -> reverse self-re-read maximizes hits.

#define HW     4096
#define C      256
#define HEADS  8
#define PLANES 64
#define SC_POS 64                       // positions per warp superchunk
#define SC_PER_BATCH (HW / SC_POS)      // 64
#define WPB    16                       // warps per block
#define THREADS (WPB * 32)              // 512
#define MAXB   64

__device__ float    g_pnum2[MAXB * SC_PER_BATCH * C];      // [gw][256]
__device__ float    g_pden2[MAXB * SC_PER_BATCH * HEADS];  // [gw][8]
__device__ float    g_term[MAXB * C];
__device__ unsigned g_cnt[2];
__device__ unsigned g_gen[2];   // monotone generation counters (replay-safe)

__device__ __forceinline__ void grid_barrier(int k, int nblocks)
{
    __threadfence();
    __syncthreads();
    if (threadIdx.x == 0) {
        const unsigned g = atomicAdd(&g_gen[k], 0u);   // read current gen
        if (atomicAdd(&g_cnt[k], 1u) == (unsigned)nblocks - 1u) {
            g_cnt[k] = 0;                               // reset for next replay
            __threadfence();
            atomicAdd(&g_gen[k], 1u);                   // release
        } else {
            while (atomicAdd(&g_gen[k], 0u) == g) __nanosleep(64);
        }
    }
    __syncthreads();
}

__global__ __launch_bounds__(THREADS, 1) void gc_fused_kernel(
    const float* __restrict__ x,  const float* __restrict__ wm,
    const float* __restrict__ bmp,
    const float* __restrict__ w1, const float* __restrict__ b1,
    const float* __restrict__ gamma, const float* __restrict__ beta,
    const float* __restrict__ w2, const float* __restrict__ b2,
    float* __restrict__ out, int B, int nblocks)
{
    const int tid = threadIdx.x;
    const int wid = tid >> 5;
    const int l   = tid & 31;

    // warp's superchunk: gw in [0, B*64)
    const int gw = blockIdx.x * WPB + wid;
    const int b  = gw / SC_PER_BATCH;
    const int s0 = (gw % SC_PER_BATCH) * SC_POS;

    __shared__ float s_ctx[C];
    __shared__ float s_y[PLANES];
    __shared__ float s_stats[2];

    // =======================  Phase 1: pooling partials  ====================
    // Lane l covers channels 4l..4l+3 (half 0) and 128+4l.. (half 1).
    // 8-lane group j -> head j (half0) / head 4+j (half1). wm idx = 4*(l&7).
    {
        const float4 wmv = *reinterpret_cast<const float4*>(wm + 4 * (l & 7));
        const float  bm  = bmp[0];
        const float* base = x + ((size_t)b * HW + s0) * C + 4 * l;

        float4 acc0 = make_float4(0.f, 0.f, 0.f, 0.f);
        float4 acc1 = make_float4(0.f, 0.f, 0.f, 0.f);
        float  den0 = 0.f, den1 = 0.f;

        for (int it = 0; it < SC_POS / 4; it++) {
            float4 xv0[4], xv1[4];
            #pragma unroll
            for (int i = 0; i < 4; i++) {
                const float* p = base + (size_t)(it * 4 + i) * C;
                xv0[i] = *reinterpret_cast<const float4*>(p);
                xv1[i] = *reinterpret_cast<const float4*>(p + 128);
            }
            float lg[8];
            #pragma unroll
            for (int i = 0; i < 4; i++) {
                lg[i]     = xv0[i].x*wmv.x + xv0[i].y*wmv.y + xv0[i].z*wmv.z + xv0[i].w*wmv.w;
                lg[4 + i] = xv1[i].x*wmv.x + xv1[i].y*wmv.y + xv1[i].z*wmv.z + xv1[i].w*wmv.w;
            }
            #pragma unroll
            for (int u = 0; u < 8; u++) lg[u] += __shfl_xor_sync(0xFFFFFFFFu, lg[u], 1);
            #pragma unroll
            for (int u = 0; u < 8; u++) lg[u] += __shfl_xor_sync(0xFFFFFFFFu, lg[u], 2);
            #pragma unroll
            for (int u = 0; u < 8; u++) lg[u] += __shfl_xor_sync(0xFFFFFFFFu, lg[u], 4);

            float e[8];
            #pragma unroll
            for (int u = 0; u < 8; u++) e[u] = __expf(lg[u] + bm);

            #pragma unroll
            for (int i = 0; i < 4; i++) {
                acc0.x = fmaf(e[i], xv0[i].x, acc0.x);
                acc0.y = fmaf(e[i], xv0[i].y, acc0.y);
                acc0.z = fmaf(e[i], xv0[i].z, acc0.z);
                acc0.w = fmaf(e[i], xv0[i].w, acc0.w);
                den0  += e[i];
                acc1.x = fmaf(e[4+i], xv1[i].x, acc1.x);
                acc1.y = fmaf(e[4+i], xv1[i].y, acc1.y);
                acc1.z = fmaf(e[4+i], xv1[i].z, acc1.z);
                acc1.w = fmaf(e[4+i], xv1[i].w, acc1.w);
                den1  += e[4+i];
            }
        }

        float* pn = g_pnum2 + (size_t)gw * C;
        *reinterpret_cast<float4*>(pn + 4 * l)       = acc0;
        *reinterpret_cast<float4*>(pn + 128 + 4 * l) = acc1;
        if ((l & 7) == 0) {
            g_pden2[gw * HEADS + (l >> 3)]     = den0;   // heads 0..3
            g_pden2[gw * HEADS + 4 + (l >> 3)] = den1;   // heads 4..7
        }
    }

    grid_barrier(0, nblocks);

    // =======================  MLP (blocks 0..B-1)  ==========================
    if (blockIdx.x < B) {
        const int bb = blockIdx.x;
        if (tid < C) {
            const int c = tid, head = c >> 5;
            float num = 0.f, den = 0.f;
            #pragma unroll 16
            for (int k = 0; k < SC_PER_BATCH; k++) {
                num += g_pnum2[(size_t)(bb * SC_PER_BATCH + k) * C + c];
                den += g_pden2[(bb * SC_PER_BATCH + k) * HEADS + head];
            }
            s_ctx[c] = num / den;
        }
        __syncthreads();

        if (tid < C) {                     // y = ctx @ w1 + b1
            const int p = tid >> 2, q = tid & 3;
            float acc = 0.f;
            #pragma unroll 8
            for (int i = 0; i < 64; i++) {
                const int c = q * 64 + i;
                acc = fmaf(s_ctx[c], w1[c * PLANES + p], acc);
            }
            acc += __shfl_xor_sync(0xFFFFFFFFu, acc, 1);
            acc += __shfl_xor_sync(0xFFFFFFFFu, acc, 2);
            if (q == 0) s_y[p] = acc + b1[p];
        }
        __syncthreads();

        if (tid < 32) {                    // LN stats over 64 planes
            const float v1 = s_y[tid], v2 = s_y[tid + 32];
            float s = v1 + v2, sq = v1 * v1 + v2 * v2;
            #pragma unroll
            for (int m = 16; m > 0; m >>= 1) {
                s  += __shfl_xor_sync(0xFFFFFFFFu, s,  m);
                sq += __shfl_xor_sync(0xFFFFFFFFu, sq, m);
            }
            if (tid == 0) {
                const float mean = s / 64.f;
                const float var  = sq / 64.f - mean * mean;
                s_stats[0] = mean;
                s_stats[1] = rsqrtf(var + 1e-3f);
            }
        }
        __syncthreads();

        if (tid < PLANES) {                // normalize + relu
            const float v = (s_y[tid] - s_stats[0]) * s_stats[1] * gamma[tid] + beta[tid];
            s_y[tid] = fmaxf(v, 0.f);
        }
        __syncthreads();

        if (tid < C) {                     // term = y @ w2 + b2
            const int c = tid;
            float acc = b2[c];
            #pragma unroll 8
            for (int p = 0; p < PLANES; p++)
                acc = fmaf(s_y[p], w2[p * C + c], acc);
            g_term[bb * C + c] = acc;
        }
    }

    grid_barrier(1, nblocks);

    // ==========  Phase 2: out = x + term, reverse walk of own chunk  ========
    {
        const float4 tv0 = *reinterpret_cast<const float4*>(g_term + b * C + 4 * l);
        const float4 tv1 = *reinterpret_cast<const float4*>(g_term + b * C + 128 + 4 * l);
        const float* xb = x   + ((size_t)b * HW + s0) * C + 4 * l;
        float*       ob = out + ((size_t)b * HW + s0) * C + 4 * l;

        for (int it = SC_POS / 4 - 1; it >= 0; it--) {
            float4 v0[4], v1[4];
            #pragma unroll
            for (int i = 0; i < 4; i++) {
                const float* p = xb + (size_t)(it * 4 + i) * C;
                v0[i] = *reinterpret_cast<const float4*>(p);
                v1[i] = *reinterpret_cast<const float4*>(p + 128);
            }
            #pragma unroll
            for (int i = 0; i < 4; i++) {
                float* q = ob + (size_t)(it * 4 + i) * C;
                float4 a = v0[i];
                a.x += tv0.x; a.y += tv0.y; a.z += tv0.z; a.w += tv0.w;
                __stcs(reinterpret_cast<float4*>(q), a);
                float4 c2 = v1[i];
                c2.x += tv1.x; c2.y += tv1.y; c2.z += tv1.z; c2.w += tv1.w;
                __stcs(reinterpret_cast<float4*>(q + 128), c2);
            }
        }
    }
}

extern "C" void kernel_launch(void* const* d_in, const int* in_sizes, int n_in,
                              void* d_out, int out_size)
{
    const float* x     = (const float*)d_in[0];
    const float* wm    = (const float*)d_in[1];
    const float* bm    = (const float*)d_in[2];
    const float* w1    = (const float*)d_in[3];
    const float* b1    = (const float*)d_in[4];
    const float* gamma = (const float*)d_in[5];
    const float* beta  = (const float*)d_in[6];
    const float* w2    = (const float*)d_in[7];
    const float* b2    = (const float*)d_in[8];
    float* out = (float*)d_out;

    const int B = in_sizes[0] / (HW * C);   // 32
    const int nblocks = B * 4;              // 128 <= 148 SMs -> co-resident

    gc_fused_kernel<<<nblocks, THREADS>>>(x, wm, bm, w1, b1, gamma, beta,
                                          w2, b2, out, B, nblocks);
}